// round 14
// baseline (speedup 1.0000x reference)
#include <cuda_runtime.h>
#include <cstddef>

#define NF 510
#define BB 32
#define HH 4
#define DD 64

// ---------------- scratch (__device__ globals; no allocation allowed) ----------------
__device__ float  g_xt[(size_t)BB*NF*256];        // xt[b][n][h*64+d]
__device__ float  g_si[BB*HH*NF];                 // s_i[b][h][n]
__device__ float  g_sj[BB*HH*NF];                 // s_j[b][h][n]
__device__ float4 g_cc[(size_t)NF*NF];            // 0.9*(conv3x3(causal, w[:,1]) + bias)
__device__ float  g_outp[4][(size_t)BB*NF*DD];    // per-head partial A_h @ xt_h

// ---- packed f32x2 helpers (FFMA2: 2 MACs / instruction) ----
__device__ __forceinline__ void ffma2(unsigned long long& d, unsigned long long a, unsigned long long b) {
    asm("fma.rn.f32x2 %0, %1, %2, %0;" : "+l"(d) : "l"(a), "l"(b));
}

// ---------------- K1: xt = x @ W   (16320x64 @ 64x256) ----------------
__global__ __launch_bounds__(256) void k_xt(const float* __restrict__ x,
                                            const float* __restrict__ W) {
    __shared__ __align__(16) float xs[16][64];
    int c = threadIdx.x;
    size_t base = (size_t)blockIdx.x * (16 * 64);
#pragma unroll
    for (int i = 0; i < 4; i++) {
        int idx = c + i * 256;
        xs[idx >> 6][idx & 63] = x[base + idx];
    }
    __syncthreads();
    float acc[16];
#pragma unroll
    for (int r = 0; r < 16; r++) acc[r] = 0.f;
    for (int kc = 0; kc < 16; kc++) {
        float w0 = W[(kc * 4 + 0) * 256 + c];
        float w1 = W[(kc * 4 + 1) * 256 + c];
        float w2 = W[(kc * 4 + 2) * 256 + c];
        float w3 = W[(kc * 4 + 3) * 256 + c];
#pragma unroll
        for (int r = 0; r < 16; r++) {
            float4 xv = *(const float4*)&xs[r][kc * 4];
            acc[r] = fmaf(xv.x, w0, acc[r]);
            acc[r] = fmaf(xv.y, w1, acc[r]);
            acc[r] = fmaf(xv.z, w2, acc[r]);
            acc[r] = fmaf(xv.w, w3, acc[r]);
        }
    }
    size_t ob = (size_t)blockIdx.x * (16 * 256);
#pragma unroll
    for (int r = 0; r < 16; r++) g_xt[ob + r * 256 + c] = acc[r];
}

// ---------------- K2: s_i, s_j (one warp per (b,n) row) ----------------
__global__ __launch_bounds__(256) void k_s(const float* __restrict__ attw) {
    __shared__ float aw[512];
    int tid = threadIdx.x;
    aw[tid] = attw[tid];
    aw[tid + 256] = attw[tid + 256];
    __syncthreads();
    int w = tid >> 5, lane = tid & 31;
    int row = blockIdx.x * 8 + w;
    const float* xr = g_xt + (size_t)row * 256;
    float xv[8];
#pragma unroll
    for (int j = 0; j < 8; j++) xv[j] = xr[lane + 32 * j];
    int b = row / NF, n = row % NF;
#pragma unroll
    for (int h = 0; h < 4; h++) {
        float si = xv[2*h] * aw[h*128 + lane] + xv[2*h+1] * aw[h*128 + 32 + lane];
        float sj = xv[2*h] * aw[h*128 + 64 + lane] + xv[2*h+1] * aw[h*128 + 96 + lane];
#pragma unroll
        for (int o = 16; o; o >>= 1) {
            si += __shfl_xor_sync(0xffffffffu, si, o);
            sj += __shfl_xor_sync(0xffffffffu, sj, o);
        }
        if (!lane) {
            g_si[(b * 4 + h) * NF + n] = si;
            g_sj[(b * 4 + h) * NF + n] = sj;
        }
    }
}

// ---------------- K2b: Cc = 0.9*(conv3x3(causal, w[:,1,:,:]) + bias), batch-invariant ----------------
__global__ __launch_bounds__(512) void k_cc(const float* __restrict__ causal,
                                            const float* __restrict__ cw,
                                            const float* __restrict__ cb) {
    __shared__ float cs[3][512];
    __shared__ float w1s[36];
    __shared__ float cbs[4];
    int m = threadIdx.x, n = blockIdx.x;
    if (m < 36) w1s[m] = 0.9f * cw[(m / 9) * 18 + 9 + (m % 9)];
    if (m < 4)  cbs[m] = 0.9f * cb[m];
#pragma unroll
    for (int ky = 0; ky < 3; ky++) {
        int rr = n + ky - 1;
        if (m < NF) cs[ky][m + 1] = (rr >= 0 && rr < NF) ? causal[rr * NF + m] : 0.f;
        else        cs[ky][m == NF ? 0 : 511] = 0.f;
    }
    __syncthreads();
    if (m < NF) {
        float c[9];
#pragma unroll
        for (int ky = 0; ky < 3; ky++)
#pragma unroll
            for (int kx = 0; kx < 3; kx++) c[ky * 3 + kx] = cs[ky][m + kx];
        float o[4];
#pragma unroll
        for (int h = 0; h < 4; h++) {
            float v = cbs[h];
#pragma unroll
            for (int j = 0; j < 9; j++) v = fmaf(w1s[h * 9 + j], c[j], v);
            o[h] = v;
        }
        g_cc[n * NF + m] = make_float4(o[0], o[1], o[2], o[3]);
    }
}

// ---------------- K3: warp-pair-per-row, e in registers, A written ONCE; 3-way split FMA chains ----
// block = 512 thr = 16 warps = 8 rows x 2 head-slots.
__global__ __launch_bounds__(512, 2) void k_attn(const float* __restrict__ cw,
                                                 float* __restrict__ Aout) {
    __shared__ float amean[10][520];   // conv input rows r0-1 .. r0+8; col = m+1
    __shared__ float sjs[4][512];      // s_j per head (cols 510,511 = 0)
    __shared__ float sis[10][4];       // s_i rows r0-1 .. r0+8
    __shared__ float w0s[36];

    int tid = threadIdx.x;
    int b = blockIdx.y;
    int r0 = blockIdx.x * 8;
    int wid = tid >> 5, lane = tid & 31;
    int rt = wid >> 1;                 // row in tile 0..7
    int slot = wid & 1;                // head pair

#pragma unroll
    for (int h = 0; h < 4; h++)
        sjs[h][tid] = (tid < NF) ? g_sj[(b * 4 + h) * NF + tid] : 0.f;
    if (tid < 40) {
        int rr = tid >> 2, h = tid & 3;
        int row = r0 - 1 + rr;
        sis[rr][h] = ((unsigned)row < NF) ? g_si[(b * 4 + h) * NF + row] : 0.f;
    }
    if (tid < 36) w0s[tid] = 0.225f * cw[(tid / 9) * 18 + (tid % 9)];  // 0.9*0.25 folded
    __syncthreads();

    {
        float sjl[4];
#pragma unroll
        for (int h = 0; h < 4; h++) sjl[h] = sjs[h][tid];
        bool mok = tid < NF;
#pragma unroll
        for (int rr = 0; rr < 10; rr++) {
            int row = r0 - 1 + rr;
            float v = 0.f;
            if (mok && (unsigned)row < NF) {
#pragma unroll
                for (int h = 0; h < 4; h++) {
                    float t = sis[rr][h] + sjl[h];
                    v += fmaxf(t, 0.01f * t);
                }
            }
            amean[rr][tid + 1] = v;
        }
        if (tid < 10) { amean[tid][0] = 0.f; amean[tid][513] = 0.f; }
    }
    __syncthreads();

    int n = r0 + rt;
    if (n >= NF) return;

    int h0 = slot * 2;
    float si0 = sis[rt + 1][h0], si1 = sis[rt + 1][h0 + 1];
    const float* wh0 = &w0s[h0 * 9];
    const float* wh1 = &w0s[(h0 + 1) * 9];
    const float* ccp = (const float*)g_cc + ((size_t)n * NF) * 4 + slot * 2;  // + m*4

    float e0[16], e1[16];
    float sum0 = 0.f, sum1 = 0.f;
#pragma unroll
    for (int c = 0; c < 16; c++) {
        int m = c * 32 + lane;
        bool mval = m < NF;
        float t00 = amean[rt][m],     t01 = amean[rt][m + 1],     t02 = amean[rt][m + 2];
        float t10 = amean[rt + 1][m], t11 = amean[rt + 1][m + 1], t12 = amean[rt + 1][m + 2];
        float t20 = amean[rt + 2][m], t21 = amean[rt + 2][m + 1], t22 = amean[rt + 2][m + 2];
        float2 cc = make_float2(0.f, 0.f);
        if (mval) cc = *(const float2*)&ccp[(size_t)m * 4];
        // 3 independent partial chains per head (ILP 6 across the head pair)
        float p0a = fmaf(wh0[0], t00, fmaf(wh0[1], t01, wh0[2] * t02));
        float p0b = fmaf(wh0[3], t10, fmaf(wh0[4], t11, wh0[5] * t12));
        float p0c = fmaf(wh0[6], t20, fmaf(wh0[7], t21, fmaf(wh0[8], t22, cc.x)));
        float p1a = fmaf(wh1[0], t00, fmaf(wh1[1], t01, wh1[2] * t02));
        float p1b = fmaf(wh1[3], t10, fmaf(wh1[4], t11, wh1[5] * t12));
        float p1c = fmaf(wh1[6], t20, fmaf(wh1[7], t21, fmaf(wh1[8], t22, cc.y)));
        float tt0 = si0 + sjs[h0][m];
        float tt1 = si1 + sjs[h0 + 1][m];
        float lg0 = fmaf(0.1f, fmaxf(tt0, 0.01f * tt0), (p0a + p0b) + p0c);
        float lg1 = fmaf(0.1f, fmaxf(tt1, 0.01f * tt1), (p1a + p1b) + p1c);
        e0[c] = mval ? __expf(lg0) : 0.f;   // logits bounded far below fp32 exp overflow
        e1[c] = mval ? __expf(lg1) : 0.f;
        sum0 += e0[c]; sum1 += e1[c];
    }
#pragma unroll
    for (int o = 16; o; o >>= 1) {
        sum0 += __shfl_xor_sync(0xffffffffu, sum0, o);
        sum1 += __shfl_xor_sync(0xffffffffu, sum1, o);
    }
    float i0 = 1.0f / sum0, i1 = 1.0f / sum1;
    size_t base0 = ((size_t)(b * 4 + h0) * NF + n) * NF;
    size_t base1 = base0 + (size_t)NF * NF;
#pragma unroll
    for (int c = 0; c < 16; c++) {
        int m = c * 32 + lane;
        if (m < NF) {
            Aout[base0 + m] = e0[c] * i0;
            Aout[base1 + m] = e1[c] * i1;
        }
    }
}

// ---------------- K4: per-head partial = A_h @ xt_h ----------------
// tile 128x64, 8x8 microtile, FFMA2 with B pre-duplicated in SMEM (no MOV packing),
// double-buffered SMEM (1 sync/iter). grid (4 row-tiles, 32 batches, 4 heads), 128 thr.
__global__ __launch_bounds__(128) void k_av(const float* __restrict__ A) {
    __shared__ __align__(16) float As[2][16 * 132];   // [k][row], pitch 132
    __shared__ __align__(16) float Bs[2][16 * 132];   // [k][col dup-pair], col c at offset 2c
    int b = blockIdx.y;
    int h = blockIdx.z;
    int r0 = blockIdx.x * 128;
    int nvalid = NF - r0; if (nvalid > 128) nvalid = 128;
    int tid = threadIdx.x;
    int tx = tid & 7, ty = tid >> 3;
    int la_k = tid & 15, la_r0 = (tid >> 4) * 16;
    int lb_c = tid & 63, lb_k0 = (tid >> 6) * 8;

    const float* Ab = A + ((size_t)(b * 4 + h) * NF + r0) * NF;
    const float* Xb = g_xt + (size_t)b * NF * 256 + h * 64;

    unsigned long long acc2[4][8];
#pragma unroll
    for (int i = 0; i < 4; i++)
#pragma unroll
        for (int j = 0; j < 8; j++) acc2[i][j] = 0ull;

    float ra[16], rb[8];
#pragma unroll
    for (int i = 0; i < 16; i++) {
        int row = la_r0 + i;
        ra[i] = (row < nvalid) ? Ab[(size_t)row * NF + la_k] : 0.f;
    }
#pragma unroll
    for (int i = 0; i < 8; i++)
        rb[i] = Xb[(size_t)(lb_k0 + i) * 256 + lb_c];

    int p = 0;
    int ty8 = ty * 8, tx16 = tx * 16;
    for (int it = 0; it < 32; it++) {
        float* asp = As[p];
        float* bsp = Bs[p];
#pragma unroll
        for (int i = 0; i < 16; i++) asp[la_k * 132 + la_r0 + i] = ra[i];
#pragma unroll
        for (int i = 0; i < 8; i++)
            *(float2*)&bsp[(lb_k0 + i) * 132 + lb_c * 2] = make_float2(rb[i], rb[i]);
        __syncthreads();
        if (it + 1 < 32) {
            int k0 = (it + 1) * 16;
#pragma unroll
            for (int i = 0; i < 16; i++) {
                int row = la_r0 + i;
                ra[i] = (row < nvalid && k0 + la_k < NF) ? Ab[(size_t)row * NF + k0 + la_k] : 0.f;
            }
#pragma unroll
            for (int i = 0; i < 8; i++) {
                int k = k0 + lb_k0 + i;
                rb[i] = (k < NF) ? Xb[(size_t)k * 256 + lb_c] : 0.f;
            }
        }
#pragma unroll
        for (int kk = 0; kk < 16; kk++) {
            ulonglong2 aA = *(const ulonglong2*)&asp[kk * 132 + ty8];      // rows 0-1, 2-3
            ulonglong2 aB = *(const ulonglong2*)&asp[kk * 132 + ty8 + 4];  // rows 4-5, 6-7
            ulonglong2 b0 = *(const ulonglong2*)&bsp[kk * 132 + tx16];
            ulonglong2 b1 = *(const ulonglong2*)&bsp[kk * 132 + tx16 + 4];
            ulonglong2 b2 = *(const ulonglong2*)&bsp[kk * 132 + tx16 + 8];
            ulonglong2 b3 = *(const ulonglong2*)&bsp[kk * 132 + tx16 + 12];
            unsigned long long bp[8] = {b0.x, b0.y, b1.x, b1.y, b2.x, b2.y, b3.x, b3.y};
#pragma unroll
            for (int c = 0; c < 8; c++) {
                ffma2(acc2[0][c], aA.x, bp[c]);
                ffma2(acc2[1][c], aA.y, bp[c]);
                ffma2(acc2[2][c], aB.x, bp[c]);
                ffma2(acc2[3][c], aB.y, bp[c]);
            }
        }
        p ^= 1;
        // no second barrier: next iteration stores go to the other buffer; the
        // single sync two iterations later orders reuse of this buffer.
        __syncthreads();
    }
    float* outp = g_outp[h];
#pragma unroll
    for (int j = 0; j < 4; j++) {
        union { unsigned long long u; float2 f; } cc[8];
#pragma unroll
        for (int c = 0; c < 8; c++) cc[c].u = acc2[j][c];
        int row0 = ty * 8 + 2 * j;
        if (row0 < nvalid) {
            size_t base = ((size_t)(b * NF) + r0 + row0) * 64 + tx * 8;
            *(float4*)&outp[base]     = make_float4(cc[0].f.x, cc[1].f.x, cc[2].f.x, cc[3].f.x);
            *(float4*)&outp[base + 4] = make_float4(cc[4].f.x, cc[5].f.x, cc[6].f.x, cc[7].f.x);
        }
        if (row0 + 1 < nvalid) {
            size_t base = ((size_t)(b * NF) + r0 + row0 + 1) * 64 + tx * 8;
            *(float4*)&outp[base]     = make_float4(cc[0].f.y, cc[1].f.y, cc[2].f.y, cc[3].f.y);
            *(float4*)&outp[base + 4] = make_float4(cc[4].f.y, cc[5].f.y, cc[6].f.y, cc[7].f.y);
        }
    }
}

// ---------------- K5: g = out@fcg_w + b, GLU, +x, LayerNorm  (warp per row, fw in smem) ----------------
__global__ __launch_bounds__(256) void k_fin(const float* __restrict__ x,
                                             const float* __restrict__ fw,
                                             const float* __restrict__ fb,
                                             const float* __restrict__ lng,
                                             const float* __restrict__ lnb,
                                             float* __restrict__ y) {
    __shared__ __align__(16) float fws[64 * 128];
    __shared__ float outs[8][64];
    int tid = threadIdx.x;
    {
        const float4* fw4 = (const float4*)fw;
        float4* fs4 = (float4*)fws;
#pragma unroll
        for (int i = 0; i < 8; i++) fs4[tid + i * 256] = fw4[tid + i * 256];
    }
    int r0 = blockIdx.x * 8;
#pragma unroll
    for (int i = 0; i < 2; i++) {
        int idx = tid + i * 256;
        size_t g = (size_t)r0 * 64 + idx;
        outs[idx >> 6][idx & 63] = 0.25f * (g_outp[0][g] + g_outp[1][g] + g_outp[2][g] + g_outp[3][g]);
    }
    __syncthreads();
    int w = tid >> 5, lane = tid & 31;
    int row = r0 + w;
    const float* o = outs[w];
    float a0 = fb[lane], a1 = fb[lane + 32], b0 = fb[64 + lane], b1 = fb[96 + lane];
#pragma unroll 4
    for (int k = 0; k < 64; k++) {
        float xo = o[k];
        const float* wr = fws + k * 128;
        a0 = fmaf(xo, wr[lane], a0);
        a1 = fmaf(xo, wr[lane + 32], a1);
        b0 = fmaf(xo, wr[64 + lane], b0);
        b1 = fmaf(xo, wr[96 + lane], b1);
    }
    float g0 = a0 / (1.f + __expf(-b0));
    float g1 = a1 / (1.f + __expf(-b1));
    float y0 = g0 + x[(size_t)row * 64 + lane];
    float y1 = g1 + x[(size_t)row * 64 + lane + 32];
    float s1 = y0 + y1, s2 = y0 * y0 + y1 * y1;
#pragma unroll
    for (int off = 16; off; off >>= 1) {
        s1 += __shfl_xor_sync(0xffffffffu, s1, off);
        s2 += __shfl_xor_sync(0xffffffffu, s2, off);
    }
    float mu = s1 * (1.f / 64.f);
    float var = s2 * (1.f / 64.f) - mu * mu;
    float inv = rsqrtf(var + 1e-5f);
    y[(size_t)row * 64 + lane]      = (y0 - mu) * inv * lng[lane] + lnb[lane];
    y[(size_t)row * 64 + lane + 32] = (y1 - mu) * inv * lng[lane + 32] + lnb[lane + 32];
}

extern "C" void kernel_launch(void* const* d_in, const int* in_sizes, int n_in,
                              void* d_out, int out_size) {
    const float* x      = (const float*)d_in[0];
    const float* causal = (const float*)d_in[1];
    const float* W      = (const float*)d_in[2];
    const float* attw   = (const float*)d_in[3];
    const float* cw     = (const float*)d_in[4];
    const float* cb     = (const float*)d_in[5];
    const float* fcgw   = (const float*)d_in[6];
    const float* fcgb   = (const float*)d_in[7];
    const float* lng    = (const float*)d_in[8];
    const float* lnb    = (const float*)d_in[9];

    float* y = (float*)d_out;                       // y: B*N*D
    float* A = y + (size_t)BB * NF * DD;            // A: B*H*N*N

    k_xt  <<<1020, 256>>>(x, W);
    k_s   <<<2040, 256>>>(attw);
    k_cc  <<<510, 512>>>(causal, cw, cb);
    k_attn<<<dim3(64, 32), 512>>>(cw, A);
    k_av  <<<dim3(4, 32, 4), 128>>>(A);
    k_fin <<<2040, 256>>>(x, fcgw, fcgb, lng, lnb, y);
}

// round 15
// speedup vs baseline: 3.3034x; 3.3034x over previous
#include <cuda_runtime.h>
#include <cstddef>

#define NF 510
#define BB 32
#define HH 4
#define DD 64

// ---------------- scratch (__device__ globals; no allocation allowed) ----------------
__device__ float  g_xt[(size_t)BB*NF*256];        // xt[b][n][h*64+d]
__device__ float  g_si[BB*HH*NF];                 // s_i[b][h][n]
__device__ float  g_sj[BB*HH*NF];                 // s_j[b][h][n]
__device__ float4 g_cc[(size_t)NF*NF];            // 0.9*(conv3x3(causal, w[:,1]) + bias)
__device__ float  g_outp[4][(size_t)BB*NF*DD];    // per-head partial A_h @ xt_h

// ---- packed f32x2 helpers (FFMA2: 2 MACs / instruction) ----
__device__ __forceinline__ unsigned long long pk2(float v) {
    unsigned long long r;
    unsigned u = __float_as_uint(v);
    asm("mov.b64 %0, {%1, %1};" : "=l"(r) : "r"(u));
    return r;
}
__device__ __forceinline__ void ffma2(unsigned long long& d, unsigned long long a, unsigned long long b) {
    asm("fma.rn.f32x2 %0, %1, %2, %0;" : "+l"(d) : "l"(a), "l"(b));
}

// ---------------- K1: xt = x @ W   (16320x64 @ 64x256) ----------------
__global__ __launch_bounds__(256) void k_xt(const float* __restrict__ x,
                                            const float* __restrict__ W) {
    __shared__ __align__(16) float xs[16][64];
    int c = threadIdx.x;
    size_t base = (size_t)blockIdx.x * (16 * 64);
#pragma unroll
    for (int i = 0; i < 4; i++) {
        int idx = c + i * 256;
        xs[idx >> 6][idx & 63] = x[base + idx];
    }
    __syncthreads();
    float acc[16];
#pragma unroll
    for (int r = 0; r < 16; r++) acc[r] = 0.f;
    for (int kc = 0; kc < 16; kc++) {
        float w0 = W[(kc * 4 + 0) * 256 + c];
        float w1 = W[(kc * 4 + 1) * 256 + c];
        float w2 = W[(kc * 4 + 2) * 256 + c];
        float w3 = W[(kc * 4 + 3) * 256 + c];
#pragma unroll
        for (int r = 0; r < 16; r++) {
            float4 xv = *(const float4*)&xs[r][kc * 4];
            acc[r] = fmaf(xv.x, w0, acc[r]);
            acc[r] = fmaf(xv.y, w1, acc[r]);
            acc[r] = fmaf(xv.z, w2, acc[r]);
            acc[r] = fmaf(xv.w, w3, acc[r]);
        }
    }
    size_t ob = (size_t)blockIdx.x * (16 * 256);
#pragma unroll
    for (int r = 0; r < 16; r++) g_xt[ob + r * 256 + c] = acc[r];
}

// ---------------- K2: s_i, s_j (one warp per (b,n) row) ----------------
__global__ __launch_bounds__(256) void k_s(const float* __restrict__ attw) {
    __shared__ float aw[512];
    int tid = threadIdx.x;
    aw[tid] = attw[tid];
    aw[tid + 256] = attw[tid + 256];
    __syncthreads();
    int w = tid >> 5, lane = tid & 31;
    int row = blockIdx.x * 8 + w;
    const float* xr = g_xt + (size_t)row * 256;
    float xv[8];
#pragma unroll
    for (int j = 0; j < 8; j++) xv[j] = xr[lane + 32 * j];
    int b = row / NF, n = row % NF;
#pragma unroll
    for (int h = 0; h < 4; h++) {
        float si = xv[2*h] * aw[h*128 + lane] + xv[2*h+1] * aw[h*128 + 32 + lane];
        float sj = xv[2*h] * aw[h*128 + 64 + lane] + xv[2*h+1] * aw[h*128 + 96 + lane];
#pragma unroll
        for (int o = 16; o; o >>= 1) {
            si += __shfl_xor_sync(0xffffffffu, si, o);
            sj += __shfl_xor_sync(0xffffffffu, sj, o);
        }
        if (!lane) {
            g_si[(b * 4 + h) * NF + n] = si;
            g_sj[(b * 4 + h) * NF + n] = sj;
        }
    }
}

// ---------------- K2b: Cc = 0.9*(conv3x3(causal, w[:,1,:,:]) + bias), batch-invariant ----------------
__global__ __launch_bounds__(512) void k_cc(const float* __restrict__ causal,
                                            const float* __restrict__ cw,
                                            const float* __restrict__ cb) {
    __shared__ float cs[3][512];
    __shared__ float w1s[36];
    __shared__ float cbs[4];
    int m = threadIdx.x, n = blockIdx.x;
    if (m < 36) w1s[m] = 0.9f * cw[(m / 9) * 18 + 9 + (m % 9)];
    if (m < 4)  cbs[m] = 0.9f * cb[m];
#pragma unroll
    for (int ky = 0; ky < 3; ky++) {
        int rr = n + ky - 1;
        if (m < NF) cs[ky][m + 1] = (rr >= 0 && rr < NF) ? causal[rr * NF + m] : 0.f;
        else        cs[ky][m == NF ? 0 : 511] = 0.f;
    }
    __syncthreads();
    if (m < NF) {
        float c[9];
#pragma unroll
        for (int ky = 0; ky < 3; ky++)
#pragma unroll
            for (int kx = 0; kx < 3; kx++) c[ky * 3 + kx] = cs[ky][m + kx];
        float o[4];
#pragma unroll
        for (int h = 0; h < 4; h++) {
            float v = cbs[h];
#pragma unroll
            for (int j = 0; j < 9; j++) v = fmaf(w1s[h * 9 + j], c[j], v);
            o[h] = v;
        }
        g_cc[n * NF + m] = make_float4(o[0], o[1], o[2], o[3]);
    }
}

// ---------------- K3: warp-pair-per-row, e in registers, A written ONCE (R13 form, proven) ----------
// block = 512 thr = 16 warps = 8 rows x 2 head-slots.
__global__ __launch_bounds__(512, 2) void k_attn(const float* __restrict__ cw,
                                                 float* __restrict__ Aout) {
    __shared__ float amean[10][520];   // conv input rows r0-1 .. r0+8; col = m+1
    __shared__ float sjs[4][512];      // s_j per head (cols 510,511 = 0)
    __shared__ float sis[10][4];       // s_i rows r0-1 .. r0+8
    __shared__ float w0s[36];

    int tid = threadIdx.x;
    int b = blockIdx.y;
    int r0 = blockIdx.x * 8;
    int wid = tid >> 5, lane = tid & 31;
    int rt = wid >> 1;                 // row in tile 0..7
    int slot = wid & 1;                // head pair

#pragma unroll
    for (int h = 0; h < 4; h++)
        sjs[h][tid] = (tid < NF) ? g_sj[(b * 4 + h) * NF + tid] : 0.f;
    if (tid < 40) {
        int rr = tid >> 2, h = tid & 3;
        int row = r0 - 1 + rr;
        sis[rr][h] = ((unsigned)row < NF) ? g_si[(b * 4 + h) * NF + row] : 0.f;
    }
    if (tid < 36) w0s[tid] = 0.225f * cw[(tid / 9) * 18 + (tid % 9)];  // 0.9*0.25 folded
    __syncthreads();

    {
        float sjl[4];
#pragma unroll
        for (int h = 0; h < 4; h++) sjl[h] = sjs[h][tid];
        bool mok = tid < NF;
#pragma unroll
        for (int rr = 0; rr < 10; rr++) {
            int row = r0 - 1 + rr;
            float v = 0.f;
            if (mok && (unsigned)row < NF) {
#pragma unroll
                for (int h = 0; h < 4; h++) {
                    float t = sis[rr][h] + sjl[h];
                    v += fmaxf(t, 0.01f * t);
                }
            }
            amean[rr][tid + 1] = v;
        }
        if (tid < 10) { amean[tid][0] = 0.f; amean[tid][513] = 0.f; }
    }
    __syncthreads();

    int n = r0 + rt;
    if (n >= NF) return;

    int h0 = slot * 2;
    float si0 = sis[rt + 1][h0], si1 = sis[rt + 1][h0 + 1];
    const float* wh0 = &w0s[h0 * 9];
    const float* wh1 = &w0s[(h0 + 1) * 9];
    const float* ccp = (const float*)g_cc + ((size_t)n * NF) * 4 + slot * 2;  // + m*4

    float e0[16], e1[16];
    float sum0 = 0.f, sum1 = 0.f;
#pragma unroll
    for (int c = 0; c < 16; c++) {
        int m = c * 32 + lane;
        bool mval = m < NF;
        float t00 = amean[rt][m],     t01 = amean[rt][m + 1],     t02 = amean[rt][m + 2];
        float t10 = amean[rt + 1][m], t11 = amean[rt + 1][m + 1], t12 = amean[rt + 1][m + 2];
        float t20 = amean[rt + 2][m], t21 = amean[rt + 2][m + 1], t22 = amean[rt + 2][m + 2];
        float2 cc = make_float2(0.f, 0.f);
        if (mval) cc = *(const float2*)&ccp[(size_t)m * 4];
        float a0 = cc.x, a1 = cc.y;
        a0 = fmaf(wh0[0], t00, a0); a0 = fmaf(wh0[1], t01, a0); a0 = fmaf(wh0[2], t02, a0);
        a0 = fmaf(wh0[3], t10, a0); a0 = fmaf(wh0[4], t11, a0); a0 = fmaf(wh0[5], t12, a0);
        a0 = fmaf(wh0[6], t20, a0); a0 = fmaf(wh0[7], t21, a0); a0 = fmaf(wh0[8], t22, a0);
        a1 = fmaf(wh1[0], t00, a1); a1 = fmaf(wh1[1], t01, a1); a1 = fmaf(wh1[2], t02, a1);
        a1 = fmaf(wh1[3], t10, a1); a1 = fmaf(wh1[4], t11, a1); a1 = fmaf(wh1[5], t12, a1);
        a1 = fmaf(wh1[6], t20, a1); a1 = fmaf(wh1[7], t21, a1); a1 = fmaf(wh1[8], t22, a1);
        float tt0 = si0 + sjs[h0][m];
        float tt1 = si1 + sjs[h0 + 1][m];
        float lg0 = fmaf(0.1f, fmaxf(tt0, 0.01f * tt0), a0);
        float lg1 = fmaf(0.1f, fmaxf(tt1, 0.01f * tt1), a1);
        e0[c] = mval ? __expf(lg0) : 0.f;   // logits bounded far below fp32 exp overflow
        e1[c] = mval ? __expf(lg1) : 0.f;
        sum0 += e0[c]; sum1 += e1[c];
    }
#pragma unroll
    for (int o = 16; o; o >>= 1) {
        sum0 += __shfl_xor_sync(0xffffffffu, sum0, o);
        sum1 += __shfl_xor_sync(0xffffffffu, sum1, o);
    }
    float i0 = 1.0f / sum0, i1 = 1.0f / sum1;
    size_t base0 = ((size_t)(b * 4 + h0) * NF + n) * NF;
    size_t base1 = base0 + (size_t)NF * NF;
#pragma unroll
    for (int c = 0; c < 16; c++) {
        int m = c * 32 + lane;
        if (m < NF) {
            Aout[base0 + m] = e0[c] * i0;
            Aout[base1 + m] = e1[c] * i1;
        }
    }
}

// ---------------- K4: per-head partial = A_h @ xt_h  (R13 compute path + true double buffer) -----
// tile 128x64, 8x8 microtile, FFMA2 (pk2 packing); ONE __syncthreads per k-tile.
// grid (4 row-tiles, 32 batches, 4 heads) = 512 blocks, 128 threads.
__global__ __launch_bounds__(128) void k_av(const float* __restrict__ A) {
    __shared__ __align__(16) float As[2][16 * 132];   // [k][row], pitch 132
    __shared__ __align__(16) float Bs[2][16 * 68];    // [k][col], pitch 68
    int b = blockIdx.y;
    int h = blockIdx.z;
    int r0 = blockIdx.x * 128;
    int nvalid = NF - r0; if (nvalid > 128) nvalid = 128;
    int tid = threadIdx.x;
    int tx = tid & 7, ty = tid >> 3;
    int la_k = tid & 15, la_r0 = (tid >> 4) * 16;
    int lb_c = tid & 63, lb_k0 = (tid >> 6) * 8;

    const float* Ab = A + ((size_t)(b * 4 + h) * NF + r0) * NF;
    const float* Xb = g_xt + (size_t)b * NF * 256 + h * 64;

    unsigned long long acc2[4][8];
#pragma unroll
    for (int i = 0; i < 4; i++)
#pragma unroll
        for (int j = 0; j < 8; j++) acc2[i][j] = 0ull;

    float ra[16], rb[8];
#pragma unroll
    for (int i = 0; i < 16; i++) {
        int row = la_r0 + i;
        ra[i] = (row < nvalid) ? Ab[(size_t)row * NF + la_k] : 0.f;
    }
#pragma unroll
    for (int i = 0; i < 8; i++)
        rb[i] = Xb[(size_t)(lb_k0 + i) * 256 + lb_c];

    int p = 0;
    int ty8 = ty * 8, tx8 = tx * 8;
    for (int it = 0; it < 32; it++) {
        float* asp = As[p];
        float* bsp = Bs[p];
#pragma unroll
        for (int i = 0; i < 16; i++) asp[la_k * 132 + la_r0 + i] = ra[i];
#pragma unroll
        for (int i = 0; i < 8; i++) bsp[(lb_k0 + i) * 68 + lb_c] = rb[i];
        __syncthreads();
        // prefetch next k-tile while computing this one (other buffer, no hazard:
        // store(it+2, buf p) is ordered after compute(it, buf p) by sync(it+1))
        if (it + 1 < 32) {
            int k0 = (it + 1) * 16;
#pragma unroll
            for (int i = 0; i < 16; i++) {
                int row = la_r0 + i;
                ra[i] = (row < nvalid && k0 + la_k < NF) ? Ab[(size_t)row * NF + k0 + la_k] : 0.f;
            }
#pragma unroll
            for (int i = 0; i < 8; i++) {
                int k = k0 + lb_k0 + i;
                rb[i] = (k < NF) ? Xb[(size_t)k * 256 + lb_c] : 0.f;
            }
        }
#pragma unroll
        for (int kk = 0; kk < 16; kk++) {
            ulonglong2 aA = *(const ulonglong2*)&asp[kk * 132 + ty8];      // rows 0-1, 2-3
            ulonglong2 aB = *(const ulonglong2*)&asp[kk * 132 + ty8 + 4];  // rows 4-5, 6-7
            float4 bv0 = *(const float4*)&bsp[kk * 68 + tx8];
            float4 bv1 = *(const float4*)&bsp[kk * 68 + tx8 + 4];
            unsigned long long bp[8] = {pk2(bv0.x), pk2(bv0.y), pk2(bv0.z), pk2(bv0.w),
                                        pk2(bv1.x), pk2(bv1.y), pk2(bv1.z), pk2(bv1.w)};
#pragma unroll
            for (int c = 0; c < 8; c++) {
                ffma2(acc2[0][c], aA.x, bp[c]);
                ffma2(acc2[1][c], aA.y, bp[c]);
                ffma2(acc2[2][c], aB.x, bp[c]);
                ffma2(acc2[3][c], aB.y, bp[c]);
            }
        }
        p ^= 1;
    }
    float* outp = g_outp[h];
#pragma unroll
    for (int j = 0; j < 4; j++) {
        union { unsigned long long u; float2 f; } cc[8];
#pragma unroll
        for (int c = 0; c < 8; c++) cc[c].u = acc2[j][c];
        int row0 = ty * 8 + 2 * j;
        if (row0 < nvalid) {
            size_t base = ((size_t)(b * NF) + r0 + row0) * 64 + tx * 8;
            *(float4*)&outp[base]     = make_float4(cc[0].f.x, cc[1].f.x, cc[2].f.x, cc[3].f.x);
            *(float4*)&outp[base + 4] = make_float4(cc[4].f.x, cc[5].f.x, cc[6].f.x, cc[7].f.x);
        }
        if (row0 + 1 < nvalid) {
            size_t base = ((size_t)(b * NF) + r0 + row0 + 1) * 64 + tx * 8;
            *(float4*)&outp[base]     = make_float4(cc[0].f.y, cc[1].f.y, cc[2].f.y, cc[3].f.y);
            *(float4*)&outp[base + 4] = make_float4(cc[4].f.y, cc[5].f.y, cc[6].f.y, cc[7].f.y);
        }
    }
}

// ---------------- K5: g = out@fcg_w + b, GLU, +x, LayerNorm  (warp per row, fw in smem) ----------------
__global__ __launch_bounds__(256) void k_fin(const float* __restrict__ x,
                                             const float* __restrict__ fw,
                                             const float* __restrict__ fb,
                                             const float* __restrict__ lng,
                                             const float* __restrict__ lnb,
                                             float* __restrict__ y) {
    __shared__ __align__(16) float fws[64 * 128];
    __shared__ float outs[8][64];
    int tid = threadIdx.x;
    {
        const float4* fw4 = (const float4*)fw;
        float4* fs4 = (float4*)fws;
#pragma unroll
        for (int i = 0; i < 8; i++) fs4[tid + i * 256] = fw4[tid + i * 256];
    }
    int r0 = blockIdx.x * 8;
#pragma unroll
    for (int i = 0; i < 2; i++) {
        int idx = tid + i * 256;
        size_t g = (size_t)r0 * 64 + idx;
        outs[idx >> 6][idx & 63] = 0.25f * (g_outp[0][g] + g_outp[1][g] + g_outp[2][g] + g_outp[3][g]);
    }
    __syncthreads();
    int w = tid >> 5, lane = tid & 31;
    int row = r0 + w;
    const float* o = outs[w];
    float a0 = fb[lane], a1 = fb[lane + 32], b0 = fb[64 + lane], b1 = fb[96 + lane];
#pragma unroll 4
    for (int k = 0; k < 64; k++) {
        float xo = o[k];
        const float* wr = fws + k * 128;
        a0 = fmaf(xo, wr[lane], a0);
        a1 = fmaf(xo, wr[lane + 32], a1);
        b0 = fmaf(xo, wr[64 + lane], b0);
        b1 = fmaf(xo, wr[96 + lane], b1);
    }
    float g0 = a0 / (1.f + __expf(-b0));
    float g1 = a1 / (1.f + __expf(-b1));
    float y0 = g0 + x[(size_t)row * 64 + lane];
    float y1 = g1 + x[(size_t)row * 64 + lane + 32];
    float s1 = y0 + y1, s2 = y0 * y0 + y1 * y1;
#pragma unroll
    for (int off = 16; off; off >>= 1) {
        s1 += __shfl_xor_sync(0xffffffffu, s1, off);
        s2 += __shfl_xor_sync(0xffffffffu, s2, off);
    }
    float mu = s1 * (1.f / 64.f);
    float var = s2 * (1.f / 64.f) - mu * mu;
    float inv = rsqrtf(var + 1e-5f);
    y[(size_t)row * 64 + lane]      = (y0 - mu) * inv * lng[lane] + lnb[lane];
    y[(size_t)row * 64 + lane + 32] = (y1 - mu) * inv * lng[lane + 32] + lnb[lane + 32];
}

extern "C" void kernel_launch(void* const* d_in, const int* in_sizes, int n_in,
                              void* d_out, int out_size) {
    const float* x      = (const float*)d_in[0];
    const float* causal = (const float*)d_in[1];
    const float* W      = (const float*)d_in[2];
    const float* attw   = (const float*)d_in[3];
    const float* cw     = (const float*)d_in[4];
    const float* cb     = (const float*)d_in[5];
    const float* fcgw   = (const float*)d_in[6];
    const float* fcgb   = (const float*)d_in[7];
    const float* lng    = (const float*)d_in[8];
    const float* lnb    = (const float*)d_in[9];

    float* y = (float*)d_out;                       // y: B*N*D
    float* A = y + (size_t)BB * NF * DD;            // A: B*H*N*N

    k_xt  <<<1020, 256>>>(x, W);
    k_s   <<<2040, 256>>>(attw);
    k_cc  <<<510, 512>>>(causal, cw, cb);
    k_attn<<<dim3(64, 32), 512>>>(cw, A);
    k_av  <<<dim3(4, 32, 4), 128>>>(A);
    k_fin <<<2040, 256>>>(x, fcgw, fcgb, lng, lnb, y);
}